// round 8
// baseline (speedup 1.0000x reference)
#include <cuda_runtime.h>
#include <math_constants.h>

#define N 512
#define D 128
#define MARGIN 0.3f
#define TS 32
#define KS 130          // padded smem row stride (bank stride 2 -> conflict-free float2)
#define NTILES 136      // triangular 32x32 tiles

__device__ float        g_Dm[N * N];   // pairwise distances
__device__ double       g_sum  = 0.0;
__device__ int          g_cnt  = 0;
__device__ unsigned int g_done = 0u;

// ---------------------------------------------------------------------------
// K1: pairwise distances via norm trick (pure FFMA inner loop), triangular
// tiles + mirror store. 136 blocks x 256 threads, 2x2 micro-tile.
// ---------------------------------------------------------------------------
__global__ __launch_bounds__(256)
void dist_kernel(const float* __restrict__ X) {
    __shared__ __align__(16) float As[TS * KS];
    __shared__ __align__(16) float Bs[TS * KS];
    __shared__ float nrm[64];

    const int tid  = threadIdx.x;
    const int lane = tid & 31;
    const int warp = tid >> 5;
    const int b    = blockIdx.x;

    // map linear block -> lower-triangular tile (ti >= tj)
    int ti = (int)((sqrtf(8.0f * (float)b + 1.0f) - 1.0f) * 0.5f);
    while ((ti + 1) * (ti + 2) / 2 <= b) ti++;
    while (ti * (ti + 1) / 2 > b) ti--;
    const int tj = b - ti * (ti + 1) / 2;
    const int i0 = ti * TS, j0 = tj * TS;

    // stage tiles (float2, coalesced LDG, conflict-free STS)
    const float2* __restrict__ X2 = (const float2*)X;
    #pragma unroll
    for (int v = 0; v < 8; v++) {
        const int idx = tid + v * 256;       // 0..2047
        const int r = idx >> 6, c = idx & 63;
        ((float2*)(As + r * KS))[c] = X2[(i0 + r) * (D / 2) + c];
        ((float2*)(Bs + r * KS))[c] = X2[(j0 + r) * (D / 2) + c];
    }
    __syncthreads();

    // row norms: 8 rows per warp, shfl reduce
    #pragma unroll
    for (int r8 = 0; r8 < 8; r8++) {
        const int row = warp * 8 + r8;        // 0..63
        const float* src = (row < 32) ? (As + row * KS) : (Bs + (row - 32) * KS);
        const float2 v0 = ((const float2*)src)[lane];
        const float2 v1 = ((const float2*)src)[lane + 32];
        float s = v0.x * v0.x + v0.y * v0.y + v1.x * v1.x + v1.y * v1.y;
        #pragma unroll
        for (int o = 16; o > 0; o >>= 1)
            s += __shfl_xor_sync(0xffffffffu, s, o);
        if (lane == 0) nrm[row] = s;
    }
    __syncthreads();

    // 2x2 micro-tile inner products
    const int tx = tid & 15, ty = tid >> 4;
    const float* a0p = As + ty * KS;
    const float* a1p = As + (ty + 16) * KS;
    const float* b0p = Bs + tx * KS;
    const float* b1p = Bs + (tx + 16) * KS;

    float c00 = 0.f, c01 = 0.f, c10 = 0.f, c11 = 0.f;
    #pragma unroll 16
    for (int k = 0; k < D; k += 2) {
        const float2 a0 = *(const float2*)(a0p + k);
        const float2 a1 = *(const float2*)(a1p + k);
        const float2 b0 = *(const float2*)(b0p + k);
        const float2 b1 = *(const float2*)(b1p + k);
        c00 += a0.x * b0.x; c00 += a0.y * b0.y;
        c01 += a0.x * b1.x; c01 += a0.y * b1.y;
        c10 += a1.x * b0.x; c10 += a1.y * b0.y;
        c11 += a1.x * b1.x; c11 += a1.y * b1.y;
    }

    const float na0 = nrm[ty], na1 = nrm[ty + 16];
    const float nb0 = nrm[32 + tx], nb1 = nrm[32 + tx + 16];
    const float d00 = sqrtf(fmaxf(na0 + nb0 - 2.0f * c00, 0.0f));
    const float d01 = sqrtf(fmaxf(na0 + nb1 - 2.0f * c01, 0.0f));
    const float d10 = sqrtf(fmaxf(na1 + nb0 - 2.0f * c10, 0.0f));
    const float d11 = sqrtf(fmaxf(na1 + nb1 - 2.0f * c11, 0.0f));

    const int gi0 = i0 + ty, gi1 = i0 + ty + 16;
    const int gj0 = j0 + tx, gj1 = j0 + tx + 16;
    g_Dm[gi0 * N + gj0] = d00;
    g_Dm[gi0 * N + gj1] = d01;
    g_Dm[gi1 * N + gj0] = d10;
    g_Dm[gi1 * N + gj1] = d11;
    if (ti != tj) {
        g_Dm[gj0 * N + gi0] = d00;
        g_Dm[gj1 * N + gi0] = d01;
        g_Dm[gj0 * N + gi1] = d10;
        g_Dm[gj1 * N + gi1] = d11;
    }
}

// ---------------------------------------------------------------------------
// K2: warp-per-anchor triplet sum, 32 blocks x 512 threads (16 warps/block,
// 4 warps/SMSP) for latency hiding. Labels staged in smem. 32-atomic tail.
// ---------------------------------------------------------------------------
__global__ __launch_bounds__(512)
void triplet_kernel(const int* __restrict__ labels, float* __restrict__ out) {
    __shared__ int   slbl[N];
    __shared__ float posA[16][64];
    __shared__ float wsum[16];
    __shared__ int   wcnt[16];

    const int tid  = threadIdx.x;
    const int lane = tid & 31;
    const int warp = tid >> 5;
    const int i    = blockIdx.x * 16 + warp;   // anchor (32*16 = 512)

    slbl[tid] = labels[tid];                    // one coalesced pass
    __syncthreads();

    const int li = slbl[i];                     // LDS broadcast

    // Each lane owns 16 (dist, label) pairs of row i, coalesced L2 loads.
    float dn[16];
    int np = 0;
    #pragma unroll
    for (int v = 0; v < 16; v++) {
        const int k = lane + v * 32;
        const float dv = g_Dm[i * N + k];
        const int   lb = slbl[k];               // stride-1 LDS, conflict-free
        const bool isPos = (lb == li) && (k != i);
        const unsigned ball = __ballot_sync(0xffffffffu, isPos);
        if (isPos) {
            const int slot = np + __popc(ball & ((1u << lane) - 1u));
            if (slot < 64) posA[warp][slot] = dv + MARGIN;
        }
        np += __popc(ball);
        dn[v] = (lb != li) ? dv : CUDART_INF_F;  // masked -> relu & count both 0
    }
    __syncwarp();
    if (np > 64) np = 64;

    float lsum = 0.0f;
    int   lcnt = 0;
    for (int p = 0; p < np; p++) {
        const float A = posA[warp][p];          // broadcast LDS
        #pragma unroll
        for (int v = 0; v < 16; v++) {
            const float t = A - dn[v];
            if (t > 0.0f)    lsum += t;
            if (t > 1e-16f)  lcnt += 1;
        }
    }

    #pragma unroll
    for (int o = 16; o > 0; o >>= 1) {
        lsum += __shfl_xor_sync(0xffffffffu, lsum, o);
        lcnt += __shfl_xor_sync(0xffffffffu, lcnt, o);
    }
    if (lane == 0) { wsum[warp] = lsum; wcnt[warp] = lcnt; }
    __syncthreads();

    if (tid == 0) {
        float s = 0.0f; int c = 0;
        #pragma unroll
        for (int w = 0; w < 16; w++) { s += wsum[w]; c += wcnt[w]; }
        atomicAdd(&g_sum, (double)s);
        atomicAdd(&g_cnt, c);
        __threadfence();
        const unsigned ticket = atomicAdd(&g_done, 1u);
        if (ticket == (unsigned)(gridDim.x - 1)) {
            const double S = atomicAdd(&g_sum, 0.0);
            const int    C = atomicAdd(&g_cnt, 0);
            out[0] = (float)(S / ((double)C + 1e-16));
            // reset for next graph replay
            g_sum  = 0.0;
            g_cnt  = 0;
            g_done = 0u;
        }
    }
}

extern "C" void kernel_launch(void* const* d_in, const int* in_sizes, int n_in,
                              void* d_out, int out_size) {
    const float* X      = (const float*)d_in[0];   // [512, 128] fp32
    const int*   labels = (const int*)d_in[1];     // [512] int32
    float*       out    = (float*)d_out;           // scalar fp32

    dist_kernel<<<NTILES, 256>>>(X);
    triplet_kernel<<<32, 512>>>(labels, out);
}

// round 9
// speedup vs baseline: 1.0702x; 1.0702x over previous
#include <cuda_runtime.h>
#include <math_constants.h>

#define N 512
#define D 128
#define MARGIN 0.3f
#define TS 32
#define KS 130          // padded smem row stride (bank stride 2 -> conflict-free float2)
#define GRID 136        // triangular tiles; <= 148 SMs -> all co-resident
#define TPB 256

__device__ float        g_Dm[N * N];
__device__ double       g_sum  = 0.0;
__device__ int          g_cnt  = 0;
__device__ unsigned int g_bar  = 0u;
__device__ unsigned int g_done = 0u;

__global__ __launch_bounds__(TPB)
void fused_triplet_kernel(const float* __restrict__ X,
                          const int* __restrict__ labels,
                          float* __restrict__ out)
{
    __shared__ __align__(16) float As[TS * KS];
    __shared__ __align__(16) float Bs[TS * KS];
    __shared__ float nrm[64];
    __shared__ int   slbl[N];
    __shared__ float posA[8][64];
    __shared__ float wsum[8];
    __shared__ int   wcnt[8];

    const int tid  = threadIdx.x;
    const int lane = tid & 31;
    const int warp = tid >> 5;
    const int b    = blockIdx.x;

    // labels -> smem (used in phase 2)
    slbl[tid]       = labels[tid];
    slbl[tid + 256] = labels[tid + 256];

    // ---- map linear block -> lower-triangular tile (ti >= tj)
    int ti = (int)((sqrtf(8.0f * (float)b + 1.0f) - 1.0f) * 0.5f);
    while ((ti + 1) * (ti + 2) / 2 <= b) ti++;
    while (ti * (ti + 1) / 2 > b) ti--;
    const int tj = b - ti * (ti + 1) / 2;
    const int i0 = ti * TS, j0 = tj * TS;

    // ---- Phase 1a: stage tiles (float2, coalesced LDG, conflict-free STS)
    const float2* __restrict__ X2 = (const float2*)X;
    #pragma unroll
    for (int v = 0; v < 8; v++) {
        const int idx = tid + v * 256;       // 0..2047
        const int r = idx >> 6, c = idx & 63;
        ((float2*)(As + r * KS))[c] = X2[(i0 + r) * (D / 2) + c];
        ((float2*)(Bs + r * KS))[c] = X2[(j0 + r) * (D / 2) + c];
    }
    __syncthreads();

    // ---- Phase 1b: row norms (8 rows per warp, shfl reduce)
    #pragma unroll
    for (int r8 = 0; r8 < 8; r8++) {
        const int row = warp * 8 + r8;        // 0..63
        const float* src = (row < 32) ? (As + row * KS) : (Bs + (row - 32) * KS);
        const float2 v0 = ((const float2*)src)[lane];
        const float2 v1 = ((const float2*)src)[lane + 32];
        float s = v0.x * v0.x + v0.y * v0.y + v1.x * v1.x + v1.y * v1.y;
        #pragma unroll
        for (int o = 16; o > 0; o >>= 1)
            s += __shfl_xor_sync(0xffffffffu, s, o);
        if (lane == 0) nrm[row] = s;
    }
    __syncthreads();

    // ---- Phase 1c: 2x2 micro-tile inner products (pure FFMA via norm trick)
    {
        const int tx = tid & 15, ty = tid >> 4;
        const float* a0p = As + ty * KS;
        const float* a1p = As + (ty + 16) * KS;
        const float* b0p = Bs + tx * KS;
        const float* b1p = Bs + (tx + 16) * KS;

        float c00 = 0.f, c01 = 0.f, c10 = 0.f, c11 = 0.f;
        #pragma unroll 16
        for (int k = 0; k < D; k += 2) {
            const float2 a0 = *(const float2*)(a0p + k);
            const float2 a1 = *(const float2*)(a1p + k);
            const float2 b0 = *(const float2*)(b0p + k);
            const float2 b1 = *(const float2*)(b1p + k);
            c00 += a0.x * b0.x; c00 += a0.y * b0.y;
            c01 += a0.x * b1.x; c01 += a0.y * b1.y;
            c10 += a1.x * b0.x; c10 += a1.y * b0.y;
            c11 += a1.x * b1.x; c11 += a1.y * b1.y;
        }

        const float na0 = nrm[ty], na1 = nrm[ty + 16];
        const float nb0 = nrm[32 + tx], nb1 = nrm[32 + tx + 16];
        const float d00 = sqrtf(fmaxf(na0 + nb0 - 2.0f * c00, 0.0f));
        const float d01 = sqrtf(fmaxf(na0 + nb1 - 2.0f * c01, 0.0f));
        const float d10 = sqrtf(fmaxf(na1 + nb0 - 2.0f * c10, 0.0f));
        const float d11 = sqrtf(fmaxf(na1 + nb1 - 2.0f * c11, 0.0f));

        const int gi0 = i0 + ty, gi1 = i0 + ty + 16;
        const int gj0 = j0 + tx, gj1 = j0 + tx + 16;
        g_Dm[gi0 * N + gj0] = d00;
        g_Dm[gi0 * N + gj1] = d01;
        g_Dm[gi1 * N + gj0] = d10;
        g_Dm[gi1 * N + gj1] = d11;
        if (ti != tj) {
            g_Dm[gj0 * N + gi0] = d00;
            g_Dm[gj1 * N + gi0] = d01;
            g_Dm[gj0 * N + gi1] = d10;
            g_Dm[gj1 * N + gi1] = d11;
        }
    }

    // ---- Grid barrier: ONE arrive-RMW per block, then LOAD-poll (no RMW spin).
    __threadfence();                 // release: order g_Dm stores before arrive
    __syncthreads();
    if (tid == 0) {
        atomicAdd(&g_bar, 1u);
        const volatile unsigned int* bar = (const volatile unsigned int*)&g_bar;
        while (*bar < (unsigned)GRID) __nanosleep(128);
        __threadfence();             // acquire: order poll before g_Dm reads
    }
    __syncthreads();

    // ---- Phase 2: warp-per-anchor on blocks 0..63 (8 active warps/block).
    float lsum = 0.0f;
    int   lcnt = 0;
    const bool active = (b < 64);
    if (active) {
        const int i  = b * 8 + warp;          // anchor, 0..511
        const int li = slbl[i];
        float dn[16];
        int np = 0;
        #pragma unroll
        for (int v = 0; v < 16; v++) {
            const int k = lane + v * 32;
            const float dv = __ldcg(&g_Dm[i * N + k]);   // bypass L1
            const int   lb = slbl[k];
            const bool isPos = (lb == li) && (k != i);
            const unsigned ball = __ballot_sync(0xffffffffu, isPos);
            if (isPos) {
                const int slot = np + __popc(ball & ((1u << lane) - 1u));
                if (slot < 64) posA[warp][slot] = dv + MARGIN;
            }
            np += __popc(ball);
            dn[v] = (lb != li) ? dv : CUDART_INF_F;  // masked -> relu & count 0
        }
        __syncwarp();
        if (np > 64) np = 64;

        for (int p = 0; p < np; p++) {
            const float A = posA[warp][p];     // broadcast LDS
            #pragma unroll
            for (int v = 0; v < 16; v++) {
                const float t = A - dn[v];
                if (t > 0.0f)    lsum += t;
                if (t > 1e-16f)  lcnt += 1;
            }
        }

        #pragma unroll
        for (int o = 16; o > 0; o >>= 1) {
            lsum += __shfl_xor_sync(0xffffffffu, lsum, o);
            lcnt += __shfl_xor_sync(0xffffffffu, lcnt, o);
        }
        if (lane == 0) { wsum[warp] = lsum; wcnt[warp] = lcnt; }
    }
    __syncthreads();

    // ---- Finalize: atomics only from active blocks; ticket from all.
    if (tid == 0) {
        if (active) {
            float s = 0.0f; int c = 0;
            #pragma unroll
            for (int w = 0; w < 8; w++) { s += wsum[w]; c += wcnt[w]; }
            atomicAdd(&g_sum, (double)s);
            atomicAdd(&g_cnt, c);
        }
        __threadfence();
        const unsigned ticket = atomicAdd(&g_done, 1u);
        if (ticket == (unsigned)(GRID - 1)) {
            const double S = atomicAdd(&g_sum, 0.0);
            const int    C = atomicAdd(&g_cnt, 0);
            out[0] = (float)(S / ((double)C + 1e-16));
            // reset for next graph replay (all blocks past barrier & ticket)
            g_sum  = 0.0;
            g_cnt  = 0;
            g_done = 0u;
            g_bar  = 0u;
        }
    }
}

extern "C" void kernel_launch(void* const* d_in, const int* in_sizes, int n_in,
                              void* d_out, int out_size) {
    const float* X      = (const float*)d_in[0];   // [512, 128] fp32
    const int*   labels = (const int*)d_in[1];     // [512] int32
    float*       out    = (float*)d_out;           // scalar fp32

    fused_triplet_kernel<<<GRID, TPB>>>(X, labels, out);
}

// round 10
// speedup vs baseline: 1.2877x; 1.2032x over previous
#include <cuda_runtime.h>
#include <math_constants.h>

#define N 512
#define D 128
#define MARGIN 0.3f
#define TS 32
#define KS 130          // padded smem row stride (bank stride 2 -> conflict-free float2)
#define NTILES 136      // triangular 32x32 tiles

__device__ float        g_Dm[N * N];   // pairwise distances
__device__ double       g_sum  = 0.0;
__device__ int          g_cnt  = 0;
__device__ unsigned int g_done = 0u;

// ---------------------------------------------------------------------------
// K1: pairwise distances via norm trick (pure FFMA inner loop), triangular
// tiles + mirror store. 136 blocks x 256 threads, 2x2 micro-tile. (Proven.)
// ---------------------------------------------------------------------------
__global__ __launch_bounds__(256)
void dist_kernel(const float* __restrict__ X) {
    __shared__ __align__(16) float As[TS * KS];
    __shared__ __align__(16) float Bs[TS * KS];
    __shared__ float nrm[64];

    const int tid  = threadIdx.x;
    const int lane = tid & 31;
    const int warp = tid >> 5;
    const int b    = blockIdx.x;

    int ti = (int)((sqrtf(8.0f * (float)b + 1.0f) - 1.0f) * 0.5f);
    while ((ti + 1) * (ti + 2) / 2 <= b) ti++;
    while (ti * (ti + 1) / 2 > b) ti--;
    const int tj = b - ti * (ti + 1) / 2;
    const int i0 = ti * TS, j0 = tj * TS;

    const float2* __restrict__ X2 = (const float2*)X;
    #pragma unroll
    for (int v = 0; v < 8; v++) {
        const int idx = tid + v * 256;
        const int r = idx >> 6, c = idx & 63;
        ((float2*)(As + r * KS))[c] = X2[(i0 + r) * (D / 2) + c];
        ((float2*)(Bs + r * KS))[c] = X2[(j0 + r) * (D / 2) + c];
    }
    __syncthreads();

    #pragma unroll
    for (int r8 = 0; r8 < 8; r8++) {
        const int row = warp * 8 + r8;
        const float* src = (row < 32) ? (As + row * KS) : (Bs + (row - 32) * KS);
        const float2 v0 = ((const float2*)src)[lane];
        const float2 v1 = ((const float2*)src)[lane + 32];
        float s = v0.x * v0.x + v0.y * v0.y + v1.x * v1.x + v1.y * v1.y;
        #pragma unroll
        for (int o = 16; o > 0; o >>= 1)
            s += __shfl_xor_sync(0xffffffffu, s, o);
        if (lane == 0) nrm[row] = s;
    }
    __syncthreads();

    const int tx = tid & 15, ty = tid >> 4;
    const float* a0p = As + ty * KS;
    const float* a1p = As + (ty + 16) * KS;
    const float* b0p = Bs + tx * KS;
    const float* b1p = Bs + (tx + 16) * KS;

    float c00 = 0.f, c01 = 0.f, c10 = 0.f, c11 = 0.f;
    #pragma unroll 16
    for (int k = 0; k < D; k += 2) {
        const float2 a0 = *(const float2*)(a0p + k);
        const float2 a1 = *(const float2*)(a1p + k);
        const float2 b0 = *(const float2*)(b0p + k);
        const float2 b1 = *(const float2*)(b1p + k);
        c00 += a0.x * b0.x; c00 += a0.y * b0.y;
        c01 += a0.x * b1.x; c01 += a0.y * b1.y;
        c10 += a1.x * b0.x; c10 += a1.y * b0.y;
        c11 += a1.x * b1.x; c11 += a1.y * b1.y;
    }

    const float na0 = nrm[ty], na1 = nrm[ty + 16];
    const float nb0 = nrm[32 + tx], nb1 = nrm[32 + tx + 16];
    const float d00 = sqrtf(fmaxf(na0 + nb0 - 2.0f * c00, 0.0f));
    const float d01 = sqrtf(fmaxf(na0 + nb1 - 2.0f * c01, 0.0f));
    const float d10 = sqrtf(fmaxf(na1 + nb0 - 2.0f * c10, 0.0f));
    const float d11 = sqrtf(fmaxf(na1 + nb1 - 2.0f * c11, 0.0f));

    const int gi0 = i0 + ty, gi1 = i0 + ty + 16;
    const int gj0 = j0 + tx, gj1 = j0 + tx + 16;
    g_Dm[gi0 * N + gj0] = d00;
    g_Dm[gi0 * N + gj1] = d01;
    g_Dm[gi1 * N + gj0] = d10;
    g_Dm[gi1 * N + gj1] = d11;
    if (ti != tj) {
        g_Dm[gj0 * N + gi0] = d00;
        g_Dm[gj1 * N + gi0] = d01;
        g_Dm[gj0 * N + gi1] = d10;
        g_Dm[gj1 * N + gi1] = d11;
    }
}

// ---------------------------------------------------------------------------
// K2: 2 anchors per block (one per 128-thread half), 256 blocks x 256 threads
// (1.73 waves). 4 k-values per thread -> short serial chains. PDL-overlapped.
// ---------------------------------------------------------------------------
__global__ __launch_bounds__(256)
void triplet_kernel(const int* __restrict__ labels, float* __restrict__ out) {
    __shared__ int   npos[2];
    __shared__ float posA[2][64];
    __shared__ float wsum[8];
    __shared__ int   wcnt[8];

    const int tid  = threadIdx.x;
    const int lane = tid & 31;
    const int warp = tid >> 5;
    const int half = tid >> 7;        // 0 or 1
    const int ht   = tid & 127;       // thread-in-half
    const int i    = blockIdx.x * 2 + half;   // anchor (256*2 = 512)

    if (ht == 0) npos[half] = 0;

    // Overlap our launch/ramp with dist_kernel; wait before touching g_Dm.
    cudaGridDependencySynchronize();

    const int li = __ldg(&labels[i]);
    __syncthreads();                   // npos init visible

    // Each thread owns 4 (dist,label) pairs of row i, coalesced.
    float dn[4];
    #pragma unroll
    for (int v = 0; v < 4; v++) {
        const int k = ht + v * 128;
        const float dv = __ldcg(&g_Dm[i * N + k]);
        const int   lb = __ldg(&labels[k]);
        const bool isPos = (lb == li) && (k != i);
        if (isPos) {
            const int s = atomicAdd(&npos[half], 1);
            if (s < 64) posA[half][s] = dv + MARGIN;
        }
        dn[v] = (lb != li) ? dv : CUDART_INF_F;  // masked -> relu & count both 0
    }
    __syncthreads();

    int np = npos[half];
    if (np > 64) np = 64;

    float lsum = 0.0f;
    int   lcnt = 0;
    for (int p = 0; p < np; p++) {
        const float A = posA[half][p];          // broadcast LDS
        #pragma unroll
        for (int v = 0; v < 4; v++) {
            const float t = A - dn[v];
            if (t > 0.0f)    lsum += t;
            if (t > 1e-16f)  lcnt += 1;
        }
    }

    #pragma unroll
    for (int o = 16; o > 0; o >>= 1) {
        lsum += __shfl_xor_sync(0xffffffffu, lsum, o);
        lcnt += __shfl_xor_sync(0xffffffffu, lcnt, o);
    }
    if (lane == 0) { wsum[warp] = lsum; wcnt[warp] = lcnt; }
    __syncthreads();

    if (tid == 0) {
        float s = 0.0f; int c = 0;
        #pragma unroll
        for (int w = 0; w < 8; w++) { s += wsum[w]; c += wcnt[w]; }
        atomicAdd(&g_sum, (double)s);
        atomicAdd(&g_cnt, c);
        __threadfence();
        const unsigned ticket = atomicAdd(&g_done, 1u);
        if (ticket == (unsigned)(gridDim.x - 1)) {
            const double S = atomicAdd(&g_sum, 0.0);
            const int    C = atomicAdd(&g_cnt, 0);
            out[0] = (float)(S / ((double)C + 1e-16));
            // reset for next graph replay
            g_sum  = 0.0;
            g_cnt  = 0;
            g_done = 0u;
        }
    }
}

extern "C" void kernel_launch(void* const* d_in, const int* in_sizes, int n_in,
                              void* d_out, int out_size) {
    const float* X      = (const float*)d_in[0];   // [512, 128] fp32
    const int*   labels = (const int*)d_in[1];     // [512] int32
    float*       out    = (float*)d_out;           // scalar fp32

    dist_kernel<<<NTILES, 256>>>(X);

    // PDL: triplet kernel launches early (ramp overlapped with dist_kernel),
    // blocks internally at cudaGridDependencySynchronize until dist completes.
    cudaLaunchConfig_t cfg = {};
    cfg.gridDim  = dim3(256, 1, 1);
    cfg.blockDim = dim3(256, 1, 1);
    cudaLaunchAttribute attr[1];
    attr[0].id = cudaLaunchAttributeProgrammaticStreamSerialization;
    attr[0].val.programmaticStreamSerializationAllowed = 1;
    cfg.attrs = attr;
    cfg.numAttrs = 1;
    cudaLaunchKernelEx(&cfg, triplet_kernel, labels, out);
}